// round 5
// baseline (speedup 1.0000x reference)
#include <cuda_runtime.h>
#include <cstdint>

// Problem constants (from reference setup_inputs)
#define NROW 2048
#define TSTEPS 365
#define DD 16
#define HH 64
#define G4 256          // 4*H
#define NCTA 128
#define RPB 16          // rows per block (NCTA*RPB == NROW)
#define NTHR 256
#define CH 64           // m-chunk for A@q
#define NCHUNK (NROW/CH)

// Persistent device state (static globals — no allocation)
__device__ float    g_q[2][NROW][HH];   // double-buffered q_t
__device__ unsigned g_count = 0;        // barrier arrivals (self-resetting)
__device__ unsigned g_gen   = 0;        // barrier generation (monotonic across replays)

__device__ __forceinline__ float fsigmoid(float v) {
    return __fdividef(1.0f, 1.0f + __expf(-v));
}
__device__ __forceinline__ float ftanh(float v) {
    float e = __expf(-2.0f * fabsf(v));
    float t = __fdividef(1.0f - e, 1.0f + e);
    return copysignf(t, v);
}

extern "C" __global__ void __launch_bounds__(NTHR, 1)
rgcn_kernel(const float* __restrict__ x,   const float* __restrict__ A,
            const float* __restrict__ Wih, const float* __restrict__ Whh,
            const float* __restrict__ bias,const float* __restrict__ Wq,
            const float* __restrict__ bq,  const float* __restrict__ Wd,
            const float* __restrict__ bd,  float* __restrict__ out)
{
    extern __shared__ float sm[];
    float* Wih_s  = sm;                    // 16*256   = 4096
    float* Whh_s  = Wih_s  + DD*G4;        // 64*256   = 16384
    float* Wq_s   = Whh_s  + HH*G4;        // 64*64    = 4096
    float* bias_s = Wq_s   + HH*HH;        // 256
    float* bq_s   = bias_s + G4;           // 64
    float* Wd_s   = bq_s   + HH;           // 64
    float* hs     = Wd_s   + HH;           // 16*65    = 1040 (padded rows)
    float* cs     = hs     + RPB*65;       // 1040
    float* sGate  = cs     + RPB*65;       // 4*16*64  = 4096  (i,f,g,o activated)
    float* xs     = sGate  + 4*RPB*HH;     // 16*16    = 256
    float* Qs     = xs     + RPB*DD;       // 64*64    = 4096  (chunk of q; reused as reduce buf)
    float* As     = Qs     + CH*HH;        // 16*64    = 1024  (chunk of A rows)
    // total 36512 floats = 146048 bytes

    const int tid  = threadIdx.x;
    const int row0 = blockIdx.x * RPB;

    // ---- one-time loads ----
    for (int i = tid; i < DD*G4; i += NTHR) Wih_s[i] = Wih[i];
    for (int i = tid; i < HH*G4; i += NTHR) Whh_s[i] = Whh[i];
    for (int i = tid; i < HH*HH; i += NTHR) Wq_s[i]  = Wq[i];
    if (tid < G4) bias_s[tid] = bias[tid];
    if (tid < HH) { bq_s[tid] = bq[tid]; Wd_s[tid] = Wd[tid]; }
    for (int i = tid; i < RPB*65; i += NTHR) { hs[i] = 0.0f; cs[i] = 0.0f; }

    // Barrier base generation. Safe: no CTA can trigger a release before every
    // CTA of this launch has performed this read (a release needs all NCTA
    // arrivals, and each CTA reads gen0 before its first arrival).
    unsigned gen0 = 0;
    if (tid == 0) gen0 = *((volatile unsigned*)&g_gen);
    __syncthreads();

    // thread decompositions
    const int g_rg   = tid >> 6;             // gates: 4 row-groups of 4 rows
    const int g_c0   = (tid & 63) * 4;       // gates: 4 consecutive output cols
    const int p_ms   = tid >> 6;             // phase3: m-split 0..3
    const int p_rb   = ((tid >> 4) & 3) * 4; // phase3: row base (4 rows)
    const int p_cg   = tid & 15;             // phase3: col-quad

    for (int t = 0; t < TSTEPS; t++) {
        // ---- stage x_t for our rows ----
        {
            int r = tid >> 4, d = tid & 15;
            xs[r*DD + d] = x[((size_t)(row0 + r)*TSTEPS + t)*DD + d];
        }
        __syncthreads();

        // ---- gates = x_t@Wih + h@Whh + bias, activated, into sGate ----
        {
            float ga[4][4];
            #pragma unroll
            for (int rr = 0; rr < 4; rr++) {
                ga[rr][0] = bias_s[g_c0+0]; ga[rr][1] = bias_s[g_c0+1];
                ga[rr][2] = bias_s[g_c0+2]; ga[rr][3] = bias_s[g_c0+3];
            }
            const int rb = g_rg * 4;
            #pragma unroll 4
            for (int d = 0; d < DD; d++) {
                float4 w = *(const float4*)&Wih_s[d*G4 + g_c0];
                #pragma unroll
                for (int rr = 0; rr < 4; rr++) {
                    float hv = xs[(rb+rr)*DD + d];
                    ga[rr][0] += hv*w.x; ga[rr][1] += hv*w.y;
                    ga[rr][2] += hv*w.z; ga[rr][3] += hv*w.w;
                }
            }
            #pragma unroll 8
            for (int k = 0; k < HH; k++) {
                float4 w = *(const float4*)&Whh_s[k*G4 + g_c0];
                #pragma unroll
                for (int rr = 0; rr < 4; rr++) {
                    float hv = hs[(rb+rr)*65 + k];
                    ga[rr][0] += hv*w.x; ga[rr][1] += hv*w.y;
                    ga[rr][2] += hv*w.z; ga[rr][3] += hv*w.w;
                }
            }
            const int gate = g_c0 >> 6;       // 0:i 1:f 2:g 3:o
            const int kk   = g_c0 & 63;
            #pragma unroll
            for (int rr = 0; rr < 4; rr++)
                #pragma unroll
                for (int cc = 0; cc < 4; cc++) {
                    float v = ga[rr][cc];
                    v = (gate == 2) ? ftanh(v) : fsigmoid(v);
                    sGate[(gate*RPB + rb + rr)*HH + kk + cc] = v;
                }
        }

        // ---- q_t = tanh(h @ Wq + bq) -> global double buffer ----
        {
            int r = tid >> 4, k0 = (tid & 15) * 4;
            float a0 = bq_s[k0+0], a1 = bq_s[k0+1], a2 = bq_s[k0+2], a3 = bq_s[k0+3];
            #pragma unroll 8
            for (int k = 0; k < HH; k++) {
                float hv = hs[r*65 + k];
                float4 w = *(const float4*)&Wq_s[k*HH + k0];
                a0 += hv*w.x; a1 += hv*w.y; a2 += hv*w.z; a3 += hv*w.w;
            }
            float4 qv = make_float4(ftanh(a0), ftanh(a1), ftanh(a2), ftanh(a3));
            *(float4*)&g_q[t & 1][row0 + r][k0] = qv;
        }

        // ---- grid barrier (q_t visible everywhere) ----
        __syncthreads();
        if (tid == 0) {
            __threadfence();
            unsigned arr = atomicAdd(&g_count, 1);
            if (arr == NCTA - 1) {
                atomicExch(&g_count, 0);
                __threadfence();
                atomicAdd(&g_gen, 1);
            } else {
                unsigned target = (unsigned)(t + 1);
                while ((*((volatile unsigned*)&g_gen) - gen0) < target) {
                    __nanosleep(64);
                }
            }
            __threadfence();
        }
        __syncthreads();

        // ---- Aq = A[rows,:] @ q_t  (register-tiled, smem-staged) ----
        const float* qsrc = &g_q[t & 1][0][0];
        float acc[16];
        #pragma unroll
        for (int u = 0; u < 16; u++) acc[u] = 0.0f;

        for (int ch = 0; ch < NCHUNK; ch++) {
            const int m0 = ch * CH;
            // stage q chunk: 1024 float4, coalesced
            #pragma unroll
            for (int i = 0; i < 4; i++) {
                int idx = tid + i * NTHR;
                int m = idx >> 4, kq = (idx & 15) * 4;
                *(float4*)&Qs[m*HH + kq] = *(const float4*)&qsrc[(size_t)(m0 + m)*HH + kq];
            }
            // stage A chunk: 256 float4, coalesced per row
            {
                int r = tid >> 4, mq = (tid & 15) * 4;
                *(float4*)&As[r*CH + mq] = *(const float4*)&A[(size_t)(row0 + r)*NROW + m0 + mq];
            }
            __syncthreads();

            const int mib = p_ms * 16;
            #pragma unroll 8
            for (int mi = 0; mi < 16; mi++) {
                int m = mib + mi;
                float4 qv = *(const float4*)&Qs[m*HH + p_cg*4];
                float a0 = As[(p_rb+0)*CH + m];
                float a1 = As[(p_rb+1)*CH + m];
                float a2 = As[(p_rb+2)*CH + m];
                float a3 = As[(p_rb+3)*CH + m];
                acc[ 0]+=a0*qv.x; acc[ 1]+=a0*qv.y; acc[ 2]+=a0*qv.z; acc[ 3]+=a0*qv.w;
                acc[ 4]+=a1*qv.x; acc[ 5]+=a1*qv.y; acc[ 6]+=a1*qv.z; acc[ 7]+=a1*qv.w;
                acc[ 8]+=a2*qv.x; acc[ 9]+=a2*qv.y; acc[10]+=a2*qv.z; acc[11]+=a2*qv.w;
                acc[12]+=a3*qv.x; acc[13]+=a3*qv.y; acc[14]+=a3*qv.z; acc[15]+=a3*qv.w;
            }
            __syncthreads();
        }

        // ---- reduce m-split partials (reuse Qs) ----
        #pragma unroll
        for (int u = 0; u < 16; u++) Qs[tid*16 + u] = acc[u];
        __syncthreads();

        // ---- cell/hidden update ----
        #pragma unroll
        for (int i = 0; i < 4; i++) {
            int o = tid*4 + i;
            int r = o >> 6, k = o & 63;
            int base = ((r >> 2)*16 + (k >> 2))*16 + (r & 3)*4 + (k & 3);
            float aq = Qs[base] + Qs[base + 1024] + Qs[base + 2048] + Qs[base + 3072];
            float iv = sGate[(0*RPB + r)*HH + k];
            float fv = sGate[(1*RPB + r)*HH + k];
            float gv = sGate[(2*RPB + r)*HH + k];
            float ov = sGate[(3*RPB + r)*HH + k];
            float cv = fv * (cs[r*65 + k] + aq) + iv * gv;
            float hv = ov * ftanh(cv);
            cs[r*65 + k] = cv;
            hs[r*65 + k] = hv;
        }
        __syncthreads();

        // ---- out[n,t] = h . Wd + bd ----
        if (tid < RPB) {
            float a = bd[0];
            #pragma unroll 8
            for (int k = 0; k < HH; k++) a += hs[tid*65 + k] * Wd_s[k];
            out[(size_t)(row0 + tid)*TSTEPS + t] = a;
        }
        __syncthreads();
    }
}

extern "C" void kernel_launch(void* const* d_in, const int* in_sizes, int n_in,
                              void* d_out, int out_size)
{
    const float* x    = (const float*)d_in[0];
    const float* A    = (const float*)d_in[1];
    const float* Wih  = (const float*)d_in[2];
    const float* Whh  = (const float*)d_in[3];
    const float* bias = (const float*)d_in[4];
    const float* Wq   = (const float*)d_in[5];
    const float* bq   = (const float*)d_in[6];
    const float* Wd   = (const float*)d_in[7];
    const float* bd   = (const float*)d_in[8];
    float* out = (float*)d_out;

    const size_t smem_bytes = 36512 * sizeof(float);  // 146048 B
    cudaFuncSetAttribute(rgcn_kernel,
                         cudaFuncAttributeMaxDynamicSharedMemorySize,
                         (int)smem_bytes);

    rgcn_kernel<<<NCTA, NTHR, smem_bytes>>>(x, A, Wih, Whh, bias, Wq, bq, Wd, bd, out);
}

// round 6
// speedup vs baseline: 1.8039x; 1.8039x over previous
#include <cuda_runtime.h>
#include <cuda_fp16.h>
#include <cstdint>

// Problem constants (from reference setup_inputs)
#define NROW 2048
#define TSTEPS 365
#define DD 16
#define HH 64
#define G4 256          // 4*H
#define NCTA 128
#define RPB 16          // rows per block
#define NTHR 512
#define AH_STRIDE 2056  // halves per A row in smem (pad 8 => conflict-free frags)

// Persistent device state (static globals — no allocation)
__device__ __half   g_qh[2][HH][NROW];  // q_t transposed, fp16, double-buffered (512KB)
__device__ unsigned g_count = 0;        // barrier arrivals (self-resetting)
__device__ unsigned g_gen   = 0;        // barrier generation (monotonic across replays)

__device__ __forceinline__ float fsigmoid(float v) {
    return __fdividef(1.0f, 1.0f + __expf(-v));
}
__device__ __forceinline__ float ftanh(float v) {
    float e = __expf(-2.0f * fabsf(v));
    float t = __fdividef(1.0f - e, 1.0f + e);
    return copysignf(t, v);
}

#define MMA16816(C, A0, A1, A2, A3, B0, B1)                                   \
    asm volatile(                                                             \
        "mma.sync.aligned.m16n8k16.row.col.f32.f16.f16.f32 "                  \
        "{%0,%1,%2,%3}, {%4,%5,%6,%7}, {%8,%9}, {%0,%1,%2,%3};"               \
        : "+f"(C[0]), "+f"(C[1]), "+f"(C[2]), "+f"(C[3])                      \
        : "r"(A0), "r"(A1), "r"(A2), "r"(A3), "r"(B0), "r"(B1))

extern "C" __global__ void __launch_bounds__(NTHR, 1)
rgcn_kernel(const float* __restrict__ x,   const float* __restrict__ A,
            const float* __restrict__ Wih, const float* __restrict__ Whh,
            const float* __restrict__ bias,const float* __restrict__ Wq,
            const float* __restrict__ bq,  const float* __restrict__ Wd,
            const float* __restrict__ bd,  float* __restrict__ out)
{
    extern __shared__ char smraw[];
    __half* Ah_s = (__half*)smraw;                      // 16*2056 halves = 65792 B
    float*  fs   = (float*)(smraw + RPB*AH_STRIDE*2);
    float* Whh_s  = fs;                 // 16384
    float* Wih_s  = Whh_s  + 16384;     // 4096
    float* Wq_s   = Wih_s  + 4096;      // 4096
    float* bias_s = Wq_s   + 4096;      // 256
    float* bq_s   = bias_s + 256;       // 64
    float* Wd_s   = bq_s   + 64;        // 64
    float* hs     = Wd_s   + 64;        // 16*65 = 1040
    float* cs     = hs     + 1040;      // 1040
    float* sGate  = cs     + 1040;      // 4*16*64 = 4096
    float* xs     = sGate  + 4096;      // 256
    float* qloc   = xs     + 256;       // 16*64 = 1024
    float* Red    = qloc   + 1024;      // 4 kgroups * 1024 = 4096
    // fp32 region = 36512 floats; total smem = 65792 + 146048 = 211840 B

    const int tid  = threadIdx.x;
    const int row0 = blockIdx.x * RPB;

    // ---- one-time loads ----
    for (int i = tid; i < DD*G4; i += NTHR) Wih_s[i] = Wih[i];
    for (int i = tid; i < HH*G4; i += NTHR) Whh_s[i] = Whh[i];
    for (int i = tid; i < HH*HH; i += NTHR) Wq_s[i]  = Wq[i];
    if (tid < G4) bias_s[tid] = bias[tid];
    if (tid < HH) { bq_s[tid] = bq[tid]; Wd_s[tid] = Wd[tid]; }
    for (int i = tid; i < RPB*65; i += NTHR) { hs[i] = 0.0f; cs[i] = 0.0f; }

    // ---- convert this CTA's 16 rows of A to fp16 in smem (once) ----
    for (int idx = tid; idx < RPB*NROW/4; idx += NTHR) {
        int r  = idx >> 9;           // / 512
        int kq = (idx & 511) * 4;
        float4 v = *(const float4*)&A[(size_t)(row0 + r)*NROW + kq];
        __half2* dst = (__half2*)&Ah_s[r*AH_STRIDE + kq];
        dst[0] = __floats2half2_rn(v.x, v.y);
        dst[1] = __floats2half2_rn(v.z, v.w);
    }

    // Barrier base generation (safe: no release can occur before all CTAs read)
    unsigned gen0 = 0;
    if (tid == 0) gen0 = *((volatile unsigned*)&g_gen);
    __syncthreads();

    // decompositions
    const int g_rg = tid >> 6;             // gates: 8 row-pairs
    const int g_c0 = (tid & 63) * 4;       // gates: 4 output cols
    const int lane = tid & 31, wrp = tid >> 5;
    const int fg   = lane >> 2, ftig = lane & 3;   // mma fragment coords
    const int kg   = wrp >> 2,  sub  = wrp & 3;    // k-group, n-subtile

    for (int t = 0; t < TSTEPS; t++) {
        const int buf = t & 1;

        // ---- q_t = tanh(h @ Wq + bq) -> qloc (fp32) ----
        {
            int r = tid >> 5, h0 = (tid & 31) * 2;
            float a0 = bq_s[h0], a1 = bq_s[h0+1];
            #pragma unroll 8
            for (int k = 0; k < HH; k++) {
                float hv = hs[r*65 + k];
                float2 w = *(const float2*)&Wq_s[k*HH + h0];
                a0 += hv*w.x; a1 += hv*w.y;
            }
            qloc[r*HH + h0]     = ftanh(a0);
            qloc[r*HH + h0 + 1] = ftanh(a1);
        }
        __syncthreads();

        // ---- pack q (fp16, transposed) -> g_qh ; stage x_t in parallel ----
        if (tid < 128) {
            int h = tid >> 1, grp = tid & 1;
            unsigned u[4];
            #pragma unroll
            for (int j = 0; j < 4; j++) {
                unsigned lo = __half_as_ushort(__float2half_rn(qloc[(grp*8 + 2*j    )*HH + h]));
                unsigned hi = __half_as_ushort(__float2half_rn(qloc[(grp*8 + 2*j + 1)*HH + h]));
                u[j] = lo | (hi << 16);
            }
            *(uint4*)&g_qh[buf][h][row0 + grp*8] = make_uint4(u[0], u[1], u[2], u[3]);
            __threadfence();
        } else if (tid < 384) {
            int idx = tid - 128;                 // 0..255
            int r = idx >> 4, d = idx & 15;
            xs[r*DD + d] = x[((size_t)(row0 + r)*TSTEPS + t)*DD + d];
        }
        __syncthreads();

        // ---- arrive early (release fires from last arriver) ----
        if (tid == 0) {
            __threadfence();
            unsigned arr = atomicAdd(&g_count, 1);
            if (arr == NCTA - 1) {
                atomicExch(&g_count, 0);
                __threadfence();
                atomicAdd(&g_gen, 1);
            }
        }

        // ---- gates (row-local; overlaps barrier skew) ----
        {
            float ga[2][4];
            const int rb = g_rg * 2;
            #pragma unroll
            for (int rr = 0; rr < 2; rr++) {
                ga[rr][0] = bias_s[g_c0+0]; ga[rr][1] = bias_s[g_c0+1];
                ga[rr][2] = bias_s[g_c0+2]; ga[rr][3] = bias_s[g_c0+3];
            }
            #pragma unroll 4
            for (int d = 0; d < DD; d++) {
                float4 w = *(const float4*)&Wih_s[d*G4 + g_c0];
                float h0v = xs[rb*DD + d], h1v = xs[(rb+1)*DD + d];
                ga[0][0] += h0v*w.x; ga[0][1] += h0v*w.y; ga[0][2] += h0v*w.z; ga[0][3] += h0v*w.w;
                ga[1][0] += h1v*w.x; ga[1][1] += h1v*w.y; ga[1][2] += h1v*w.z; ga[1][3] += h1v*w.w;
            }
            #pragma unroll 8
            for (int k = 0; k < HH; k++) {
                float4 w = *(const float4*)&Whh_s[k*G4 + g_c0];
                float h0v = hs[rb*65 + k], h1v = hs[(rb+1)*65 + k];
                ga[0][0] += h0v*w.x; ga[0][1] += h0v*w.y; ga[0][2] += h0v*w.z; ga[0][3] += h0v*w.w;
                ga[1][0] += h1v*w.x; ga[1][1] += h1v*w.y; ga[1][2] += h1v*w.z; ga[1][3] += h1v*w.w;
            }
            const int gate = g_c0 >> 6;   // 0:i 1:f 2:g 3:o
            const int kk   = g_c0 & 63;
            #pragma unroll
            for (int rr = 0; rr < 2; rr++)
                #pragma unroll
                for (int cc = 0; cc < 4; cc++) {
                    float v = ga[rr][cc];
                    v = (gate == 2) ? ftanh(v) : fsigmoid(v);
                    sGate[(gate*RPB + rb + rr)*HH + kk + cc] = v;
                }
        }

        // ---- wait for all q_t ----
        if (tid == 0) {
            unsigned target = (unsigned)(t + 1);
            while (*((volatile unsigned*)&g_gen) - gen0 < target) __nanosleep(32);
            __threadfence();
        }
        __syncthreads();

        // ---- Aq[16x64] = A_rows(fp16, smem) @ q_t(fp16, L2) via tensor cores ----
        {
            const __half* qh = &g_qh[buf][0][0];
            float c0[4] = {0.f,0.f,0.f,0.f}, c1[4] = {0.f,0.f,0.f,0.f};
            const __half* arow0 = &Ah_s[fg*AH_STRIDE];
            const __half* arow8 = &Ah_s[(fg + 8)*AH_STRIDE];
            const int kbase = kg*512 + 2*ftig;      // kg * 32 ksteps * 16
            const int n0 = sub*16 + fg;
            #pragma unroll 4
            for (int i = 0; i < 32; i++) {
                int k0 = kbase + i*16;
                uint32_t a0 = *(const uint32_t*)(arow0 + k0);
                uint32_t a1 = *(const uint32_t*)(arow8 + k0);
                uint32_t a2 = *(const uint32_t*)(arow0 + k0 + 8);
                uint32_t a3 = *(const uint32_t*)(arow8 + k0 + 8);
                const unsigned* bp0 = (const unsigned*)(qh + (size_t)n0*NROW + k0);
                const unsigned* bp1 = (const unsigned*)(qh + (size_t)(n0 + 8)*NROW + k0);
                unsigned b00 = __ldcg(bp0), b01 = __ldcg(bp0 + 4);
                unsigned b10 = __ldcg(bp1), b11 = __ldcg(bp1 + 4);
                MMA16816(c0, a0, a1, a2, a3, b00, b01);
                MMA16816(c1, a0, a1, a2, a3, b10, b11);
            }
            // write k-group partials
            float* Rg = Red + kg*1024;
            const int col0 = sub*16 + 2*ftig;
            *(float2*)&Rg[ fg     *64 + col0    ] = make_float2(c0[0], c0[1]);
            *(float2*)&Rg[(fg + 8)*64 + col0    ] = make_float2(c0[2], c0[3]);
            *(float2*)&Rg[ fg     *64 + col0 + 8] = make_float2(c1[0], c1[1]);
            *(float2*)&Rg[(fg + 8)*64 + col0 + 8] = make_float2(c1[2], c1[3]);
        }
        __syncthreads();

        // ---- cell/hidden update (reduce 4 k-group partials) ----
        #pragma unroll
        for (int i = 0; i < 2; i++) {
            int o = tid*2 + i;
            int r = o >> 6, k = o & 63;
            float aq = Red[o] + Red[o + 1024] + Red[o + 2048] + Red[o + 3072];
            float iv = sGate[(0*RPB + r)*HH + k];
            float fv = sGate[(1*RPB + r)*HH + k];
            float gv = sGate[(2*RPB + r)*HH + k];
            float ov = sGate[(3*RPB + r)*HH + k];
            float cv = fv * (cs[r*65 + k] + aq) + iv * gv;
            float hv = ov * ftanh(cv);
            cs[r*65 + k] = cv;
            hs[r*65 + k] = hv;
        }
        __syncthreads();

        // ---- out[n,t] = h . Wd + bd ----
        if (tid < RPB) {
            float a = bd[0];
            #pragma unroll 8
            for (int k = 0; k < HH; k++) a += hs[tid*65 + k] * Wd_s[k];
            out[(size_t)(row0 + tid)*TSTEPS + t] = a;
        }
        __syncthreads();
    }
}

extern "C" void kernel_launch(void* const* d_in, const int* in_sizes, int n_in,
                              void* d_out, int out_size)
{
    const float* x    = (const float*)d_in[0];
    const float* A    = (const float*)d_in[1];
    const float* Wih  = (const float*)d_in[2];
    const float* Whh  = (const float*)d_in[3];
    const float* bias = (const float*)d_in[4];
    const float* Wq   = (const float*)d_in[5];
    const float* bq   = (const float*)d_in[6];
    const float* Wd   = (const float*)d_in[7];
    const float* bd   = (const float*)d_in[8];
    float* out = (float*)d_out;

    const size_t smem_bytes = (size_t)RPB*AH_STRIDE*2 + 36512*sizeof(float); // 211840
    cudaFuncSetAttribute(rgcn_kernel,
                         cudaFuncAttributeMaxDynamicSharedMemorySize,
                         (int)smem_bytes);

    rgcn_kernel<<<NCTA, NTHR, smem_bytes>>>(x, A, Wih, Whh, bias, Wq, bq, Wd, bd, out);
}

// round 7
// speedup vs baseline: 3.4253x; 1.8989x over previous
#include <cuda_runtime.h>
#include <cuda_fp16.h>
#include <cstdint>

// Problem constants (from reference setup_inputs)
#define NROW 2048
#define TSTEPS 365
#define DD 16
#define HH 64
#define G4 256          // 4*H
#define NCTA 128
#define RPB 16          // rows per block
#define NTHR 512

// q_t packed in MMA B-fragment order, double-buffered:
// index ((ks*4 + nb)*32 + lane), ks = k-step (16 k each), nb = 16-wide n block.
__device__ uint4    g_qpk[2][NROW/16 * 4 * 32];   // 2 * 16384 * 16B = 512 KB
__device__ unsigned g_count = 0;   // barrier arrivals (self-resetting)
__device__ unsigned g_gen   = 0;   // barrier generation (monotonic across replays)

__device__ __forceinline__ float fsigmoid(float v) {
    return __fdividef(1.0f, 1.0f + __expf(-v));
}
__device__ __forceinline__ float ftanh(float v) {
    float e = __expf(-2.0f * fabsf(v));
    float t = __fdividef(1.0f - e, 1.0f + e);
    return copysignf(t, v);
}
__device__ __forceinline__ unsigned packh2(float lo, float hi) {
    __half2 h = __floats2half2_rn(lo, hi);
    return *(unsigned*)&h;
}

#define MMA16816(C, A0, A1, A2, A3, B0, B1)                                   \
    asm volatile(                                                             \
        "mma.sync.aligned.m16n8k16.row.col.f32.f16.f16.f32 "                  \
        "{%0,%1,%2,%3}, {%4,%5,%6,%7}, {%8,%9}, {%0,%1,%2,%3};"               \
        : "+f"(C[0]), "+f"(C[1]), "+f"(C[2]), "+f"(C[3])                      \
        : "r"(A0), "r"(A1), "r"(A2), "r"(A3), "r"(B0), "r"(B1))

extern "C" __global__ void __launch_bounds__(NTHR, 1)
rgcn_kernel(const float* __restrict__ x,   const float* __restrict__ A,
            const float* __restrict__ Wih, const float* __restrict__ Whh,
            const float* __restrict__ bias,const float* __restrict__ Wq,
            const float* __restrict__ bq,  const float* __restrict__ Wd,
            const float* __restrict__ bd,  float* __restrict__ out)
{
    extern __shared__ char smraw[];
    // A rows in MMA A-fragment order: uint4 per (ks, lane): 128*32*16B = 64 KB
    uint4* As_pk = (uint4*)smraw;
    float* fs     = (float*)(smraw + 128*32*16);
    float* Whh_s  = fs;                 // 16384 floats
    float* Wih_s  = Whh_s  + 16384;     // 4096
    float* Wq_s   = Wih_s  + 4096;      // 4096
    float* bias_s = Wq_s   + 4096;      // 256
    float* bq_s   = bias_s + 256;       // 64
    float* Wd_s   = bq_s   + 64;        // 64
    float* hs     = Wd_s   + 64;        // 16*65 = 1040
    float* cs     = hs     + 1040;      // 1040
    float* sGate  = cs     + 1040;      // 4*16*64 = 4096
    float* xs     = sGate  + 4096;      // 256
    float* qloc   = xs     + 256;       // 16*64 = 1024
    float* Red    = qloc   + 1024;      // 4 kgroups * 1024 = 4096
    // fp32 region = 36512 floats = 146048 B; total = 65536 + 146048 = 211584 B

    const int tid  = threadIdx.x;
    const int row0 = blockIdx.x * RPB;

    // ---- one-time loads ----
    for (int i = tid; i < DD*G4; i += NTHR) Wih_s[i] = Wih[i];
    for (int i = tid; i < HH*G4; i += NTHR) Whh_s[i] = Whh[i];
    for (int i = tid; i < HH*HH; i += NTHR) Wq_s[i]  = Wq[i];
    if (tid < G4) bias_s[tid] = bias[tid];
    if (tid < HH) { bq_s[tid] = bq[tid]; Wd_s[tid] = Wd[tid]; }
    for (int i = tid; i < RPB*65; i += NTHR) { hs[i] = 0.0f; cs[i] = 0.0f; }

    // ---- pack this CTA's 16 A rows into fragment order (fp16), once ----
    for (int t2 = tid; t2 < 128*32; t2 += NTHR) {
        int ks = t2 >> 5, l = t2 & 31;
        int fg = l >> 2, ftig = l & 3;
        int k0 = ks*16 + 2*ftig;
        const float* r0p = &A[(size_t)(row0 + fg    )*NROW];
        const float* r8p = &A[(size_t)(row0 + fg + 8)*NROW];
        float2 v00 = *(const float2*)(r0p + k0);
        float2 v10 = *(const float2*)(r8p + k0);
        float2 v01 = *(const float2*)(r0p + k0 + 8);
        float2 v11 = *(const float2*)(r8p + k0 + 8);
        As_pk[t2] = make_uint4(packh2(v00.x, v00.y), packh2(v10.x, v10.y),
                               packh2(v01.x, v01.y), packh2(v11.x, v11.y));
    }

    // Barrier base generation (safe: no release can occur before all CTAs read)
    unsigned gen0 = 0;
    if (tid == 0) gen0 = *((volatile unsigned*)&g_gen);
    __syncthreads();

    // decompositions
    const int g_rg = tid >> 6;             // gates: 8 row-pairs
    const int g_c0 = (tid & 63) * 4;       // gates: 4 output cols
    const int lane = tid & 31, wrp = tid >> 5;
    const int fg   = lane >> 2, ftig = lane & 3;   // mma fragment coords
    const int kg   = wrp >> 2,  sub  = wrp & 3;    // k-group, n-subtile

    for (int t = 0; t < TSTEPS; t++) {
        const int buf = t & 1;

        // ---- q_t = tanh(h @ Wq + bq) -> qloc (fp32) ----
        {
            int r = tid >> 5, h0 = (tid & 31) * 2;
            float a0 = bq_s[h0], a1 = bq_s[h0+1];
            #pragma unroll 8
            for (int k = 0; k < HH; k++) {
                float hv = hs[r*65 + k];
                float2 w = *(const float2*)&Wq_s[k*HH + h0];
                a0 += hv*w.x; a1 += hv*w.y;
            }
            qloc[r*HH + h0]     = ftanh(a0);
            qloc[r*HH + h0 + 1] = ftanh(a1);
        }
        __syncthreads();

        // ---- pack q into fragment order -> g_qpk ; stage x_t in parallel ----
        if (tid < 128) {
            int nb = tid >> 5, l = tid & 31;
            int pfg = l >> 2, pft = l & 3;
            int n0 = nb*16, r0 = 2*pft;
            unsigned b00 = packh2(qloc[ r0   *HH + n0+pfg  ], qloc[(r0+1)*HH + n0+pfg  ]);
            unsigned b01 = packh2(qloc[(r0+8)*HH + n0+pfg  ], qloc[(r0+9)*HH + n0+pfg  ]);
            unsigned b10 = packh2(qloc[ r0   *HH + n0+pfg+8], qloc[(r0+1)*HH + n0+pfg+8]);
            unsigned b11 = packh2(qloc[(r0+8)*HH + n0+pfg+8], qloc[(r0+9)*HH + n0+pfg+8]);
            g_qpk[buf][(blockIdx.x*4 + nb)*32 + l] = make_uint4(b00, b01, b10, b11);
            __threadfence();
        } else if (tid < 384) {
            int idx = tid - 128;                 // 0..255
            int r = idx >> 4, d = idx & 15;
            xs[r*DD + d] = x[((size_t)(row0 + r)*TSTEPS + t)*DD + d];
        }
        __syncthreads();

        // ---- arrive early (release fires from last arriver) ----
        if (tid == 0) {
            __threadfence();
            unsigned arr = atomicAdd(&g_count, 1);
            if (arr == NCTA - 1) {
                atomicExch(&g_count, 0);
                __threadfence();
                atomicAdd(&g_gen, 1);
            }
        }

        // ---- gates (row-local; overlaps barrier skew) ----
        {
            float ga[2][4];
            const int rb = g_rg * 2;
            #pragma unroll
            for (int rr = 0; rr < 2; rr++) {
                ga[rr][0] = bias_s[g_c0+0]; ga[rr][1] = bias_s[g_c0+1];
                ga[rr][2] = bias_s[g_c0+2]; ga[rr][3] = bias_s[g_c0+3];
            }
            #pragma unroll 4
            for (int d = 0; d < DD; d++) {
                float4 w = *(const float4*)&Wih_s[d*G4 + g_c0];
                float h0v = xs[rb*DD + d], h1v = xs[(rb+1)*DD + d];
                ga[0][0] += h0v*w.x; ga[0][1] += h0v*w.y; ga[0][2] += h0v*w.z; ga[0][3] += h0v*w.w;
                ga[1][0] += h1v*w.x; ga[1][1] += h1v*w.y; ga[1][2] += h1v*w.z; ga[1][3] += h1v*w.w;
            }
            #pragma unroll 8
            for (int k = 0; k < HH; k++) {
                float4 w = *(const float4*)&Whh_s[k*G4 + g_c0];
                float h0v = hs[rb*65 + k], h1v = hs[(rb+1)*65 + k];
                ga[0][0] += h0v*w.x; ga[0][1] += h0v*w.y; ga[0][2] += h0v*w.z; ga[0][3] += h0v*w.w;
                ga[1][0] += h1v*w.x; ga[1][1] += h1v*w.y; ga[1][2] += h1v*w.z; ga[1][3] += h1v*w.w;
            }
            const int gate = g_c0 >> 6;   // 0:i 1:f 2:g 3:o
            const int kk   = g_c0 & 63;
            #pragma unroll
            for (int rr = 0; rr < 2; rr++)
                #pragma unroll
                for (int cc = 0; cc < 4; cc++) {
                    float v = ga[rr][cc];
                    v = (gate == 2) ? ftanh(v) : fsigmoid(v);
                    sGate[(gate*RPB + rb + rr)*HH + kk + cc] = v;
                }
        }

        // ---- wait for all q_t ----
        if (tid == 0) {
            unsigned target = (unsigned)(t + 1);
            while (*((volatile unsigned*)&g_gen) - gen0 < target) __nanosleep(32);
            __threadfence();
        }
        __syncthreads();

        // ---- Aq[16x64] = A_rows @ q_t via tensor cores, fragment-packed ----
        {
            float c0[4] = {0.f,0.f,0.f,0.f}, c1[4] = {0.f,0.f,0.f,0.f};
            const uint4* Bp = &g_qpk[buf][(kg*128 + sub)*32 + lane];
            const uint4* Ap = As_pk + kg*32*32 + lane;
            #pragma unroll 4
            for (int i = 0; i < 32; i++) {
                uint4 bv = __ldcg(Bp + i*128);
                uint4 av = Ap[i*32];
                MMA16816(c0, av.x, av.y, av.z, av.w, bv.x, bv.y);
                MMA16816(c1, av.x, av.y, av.z, av.w, bv.z, bv.w);
            }
            float* Rg = Red + kg*1024;
            const int col0 = sub*16 + 2*ftig;
            *(float2*)&Rg[ fg     *64 + col0    ] = make_float2(c0[0], c0[1]);
            *(float2*)&Rg[(fg + 8)*64 + col0    ] = make_float2(c0[2], c0[3]);
            *(float2*)&Rg[ fg     *64 + col0 + 8] = make_float2(c1[0], c1[1]);
            *(float2*)&Rg[(fg + 8)*64 + col0 + 8] = make_float2(c1[2], c1[3]);
        }
        __syncthreads();

        // ---- cell/hidden update (reduce 4 k-group partials) ----
        #pragma unroll
        for (int i = 0; i < 2; i++) {
            int o = tid*2 + i;
            int r = o >> 6, k = o & 63;
            float aq = Red[o] + Red[o + 1024] + Red[o + 2048] + Red[o + 3072];
            float iv = sGate[(0*RPB + r)*HH + k];
            float fv = sGate[(1*RPB + r)*HH + k];
            float gv = sGate[(2*RPB + r)*HH + k];
            float ov = sGate[(3*RPB + r)*HH + k];
            float cv = fv * (cs[r*65 + k] + aq) + iv * gv;
            float hv = ov * ftanh(cv);
            cs[r*65 + k] = cv;
            hs[r*65 + k] = hv;
        }
        __syncthreads();

        // ---- out[n,t] = h . Wd + bd ----
        if (tid < RPB) {
            float a = bd[0];
            #pragma unroll 8
            for (int k = 0; k < HH; k++) a += hs[tid*65 + k] * Wd_s[k];
            out[(size_t)(row0 + tid)*TSTEPS + t] = a;
        }
        __syncthreads();
    }
}

extern "C" void kernel_launch(void* const* d_in, const int* in_sizes, int n_in,
                              void* d_out, int out_size)
{
    const float* x    = (const float*)d_in[0];
    const float* A    = (const float*)d_in[1];
    const float* Wih  = (const float*)d_in[2];
    const float* Whh  = (const float*)d_in[3];
    const float* bias = (const float*)d_in[4];
    const float* Wq   = (const float*)d_in[5];
    const float* bq   = (const float*)d_in[6];
    const float* Wd   = (const float*)d_in[7];
    const float* bd   = (const float*)d_in[8];
    float* out = (float*)d_out;

    const size_t smem_bytes = 128*32*16 + 36512*sizeof(float); // 211584 B
    cudaFuncSetAttribute(rgcn_kernel,
                         cudaFuncAttributeMaxDynamicSharedMemorySize,
                         (int)smem_bytes);

    rgcn_kernel<<<NCTA, NTHR, smem_bytes>>>(x, A, Wih, Whh, bias, Wq, bq, Wd, bd, out);
}